// round 2
// baseline (speedup 1.0000x reference)
#include <cuda_runtime.h>
#include <cstdint>

#define N_NODES 50000
#define N_EDGES 800000
#define CLAMP_V 5.0f

// ---------------- device scratch (static allocation is allowed) ----------------
__device__ __align__(128) float g_Q[N_NODES * 64];
__device__ __align__(128) float g_K[N_NODES * 64];
__device__ __align__(128) float g_V[N_NODES * 64];
__device__ __align__(128) float g_denom[N_NODES * 8];
__device__ __align__(128) float g_agg[N_NODES * 64];
__device__ __align__(128) float g_row[N_NODES * 64];
__device__ __align__(128) float g_Wsw[64 * 128];   // swizzled E_weight: [k][lane][j]

// vectorized global f32 reduction (sm_90+)
__device__ __forceinline__ void red_add_v4(float* addr, float4 v) {
    asm volatile("red.global.add.v4.f32 [%0], {%1, %2, %3, %4};"
                 :: "l"(addr), "f"(v.x), "f"(v.y), "f"(v.z), "f"(v.w)
                 : "memory");
}

// ---------------- setup: build swizzled E weight ----------------
// Wsw[k*128 + lane*4 + j] = E_weight[(j*32+lane)*64 + k]
__global__ void setup_kernel(const float* __restrict__ E_w) {
    for (int i = threadIdx.x; i < 64 * 128; i += 256) {
        int k = i >> 7;
        int r = i & 127;
        int lane = r >> 2;
        int j = r & 3;
        g_Wsw[i] = E_w[(j * 32 + lane) * 64 + k];
    }
}

// ---------------- zero accumulators ----------------
__global__ void zero_kernel() {
    size_t tid = (size_t)blockIdx.x * blockDim.x + threadIdx.x;
    size_t nthr = (size_t)gridDim.x * blockDim.x;
    float4 z = make_float4(0.f, 0.f, 0.f, 0.f);
    for (size_t i = tid; i < (size_t)N_NODES * 64 / 4; i += nthr) {
        reinterpret_cast<float4*>(g_agg)[i] = z;
        reinterpret_cast<float4*>(g_row)[i] = z;
    }
    for (size_t i = tid; i < (size_t)N_NODES * 8 / 4; i += nthr) {
        reinterpret_cast<float4*>(g_denom)[i] = z;
    }
}

// ---------------- QKV: qkv = x @ W.T + b, split into Q/K/V [N][64] ----------------
// Block = 32-node tile. lane = node-in-tile, warp w computes outputs {w, w+8, ..., w+184}.
// Weights read via uniform __ldg float4 (L1-resident). Outputs transposed through smem
// so the global stores are coalesced.
__global__ __launch_bounds__(256, 2)
void qkv_kernel(const float* __restrict__ x, const float* __restrict__ Wq,
                const float* __restrict__ bq) {
    __shared__ __align__(16) float x_s[32][68];     // padded: conflict-free f4 row reads
    __shared__ float out_s[32][193];                // padded: conflict-free transposed writes

    int tid = threadIdx.x;
    int tile = blockIdx.x * 32;

    // stage x (coalesced)
#pragma unroll
    for (int i = 0; i < 8; i++) {
        int idx = tid + i * 256;            // 32*64 = 2048
        int n = idx >> 6, k = idx & 63;
        int node = tile + n;
        x_s[n][k] = (node < N_NODES) ? x[(size_t)node * 64 + k] : 0.f;
    }
    __syncthreads();

    int w = tid >> 5, lane = tid & 31;
    float acc[24];
#pragma unroll
    for (int t = 0; t < 24; t++) acc[t] = __ldg(&bq[w + 8 * t]);

    for (int k4 = 0; k4 < 64; k4 += 4) {
        float4 xv = *reinterpret_cast<const float4*>(&x_s[lane][k4]);
#pragma unroll
        for (int t = 0; t < 24; t++) {
            float4 wv = *reinterpret_cast<const float4*>(&Wq[(w + 8 * t) * 64 + k4]); // uniform
            acc[t] = fmaf(xv.x, wv.x, acc[t]);
            acc[t] = fmaf(xv.y, wv.y, acc[t]);
            acc[t] = fmaf(xv.z, wv.z, acc[t]);
            acc[t] = fmaf(xv.w, wv.w, acc[t]);
        }
    }

    // transpose through smem: out_s[node][o]
#pragma unroll
    for (int t = 0; t < 24; t++) out_s[lane][w + 8 * t] = acc[t];
    __syncthreads();

    // coalesced stores
    for (int i = tid; i < 32 * 64; i += 256) {
        int n = i >> 6, col = i & 63;
        int node = tile + n;
        if (node < N_NODES) {
            g_Q[(size_t)node * 64 + col] = out_s[n][col];
            g_K[(size_t)node * 64 + col] = out_s[n][64 + col];
            g_V[(size_t)node * 64 + col] = out_s[n][128 + col];
        }
    }
}

// ---------------- edge kernel: fused E-GEMM + message + unnormalized scatter ----------------
// 8 warps/block, 8 edges/warp, 64 edges/block. Exactly 12500 blocks cover 800000 edges.
__global__ __launch_bounds__(256, 2)
void edge_kernel(const float* __restrict__ conn_feat, const int* __restrict__ edge_index,
                 const float* __restrict__ Aw, const float* __restrict__ E_bias,
                 float* __restrict__ out_conn) {
    __shared__ __align__(16) float Wsw_s[64 * 128];     // 32 KB
    __shared__ __align__(16) float cf_s[8][8][32];      // 8 KB (k-tiled activations)
    __shared__ __align__(16) float xch[8][160];         // 5 KB (RED packing exchange)

    int tid = threadIdx.x;

    // stage swizzled weights (coalesced, identity layout)
#pragma unroll
    for (int i = 0; i < 32; i++) Wsw_s[tid + 256 * i] = g_Wsw[tid + 256 * i];
    __syncthreads();

    int w = tid >> 5, lane = tid & 31;
    int h = lane >> 3, d = lane & 7;

    float b0 = E_bias[lane];
    float b1 = E_bias[lane + 32];
    float b2 = E_bias[lane + 64];
    float b3 = E_bias[lane + 96];
    float aw_a = __ldg(&Aw[d * 8 + h]);        // Aw[d][h]     -> head h   (cols 0..31)
    float aw_b = __ldg(&Aw[d * 8 + h + 4]);    // Aw[d][h+4]   -> head h+4 (cols 32..63)

    size_t e_base = ((size_t)blockIdx.x * 8 + w) * 8;

    float acc[8][4];
#pragma unroll
    for (int e = 0; e < 8; e++) {
        acc[e][0] = b0; acc[e][1] = b1; acc[e][2] = b2; acc[e][3] = b3;
    }

    // ---- GEMM: Eh[e][j*32+lane] = bias + sum_k cf[e][k] * W[(j*32+lane)][k] ----
    for (int kt = 0; kt < 64; kt += 32) {
        __syncwarp();
#pragma unroll
        for (int e = 0; e < 8; e++)
            cf_s[w][e][lane] = conn_feat[(e_base + e) * 64 + kt + lane];
        __syncwarp();
        for (int k4 = 0; k4 < 32; k4 += 4) {
            int kk = kt + k4;
            float4 w0 = *reinterpret_cast<const float4*>(&Wsw_s[(kk + 0) * 128 + lane * 4]);
            float4 w1 = *reinterpret_cast<const float4*>(&Wsw_s[(kk + 1) * 128 + lane * 4]);
            float4 w2 = *reinterpret_cast<const float4*>(&Wsw_s[(kk + 2) * 128 + lane * 4]);
            float4 w3 = *reinterpret_cast<const float4*>(&Wsw_s[(kk + 3) * 128 + lane * 4]);
#pragma unroll
            for (int e = 0; e < 8; e++) {
                float4 c = *reinterpret_cast<const float4*>(&cf_s[w][e][k4]); // broadcast
                acc[e][0] = fmaf(c.x, w0.x, acc[e][0]);
                acc[e][0] = fmaf(c.y, w1.x, acc[e][0]);
                acc[e][0] = fmaf(c.z, w2.x, acc[e][0]);
                acc[e][0] = fmaf(c.w, w3.x, acc[e][0]);
                acc[e][1] = fmaf(c.x, w0.y, acc[e][1]);
                acc[e][1] = fmaf(c.y, w1.y, acc[e][1]);
                acc[e][1] = fmaf(c.z, w2.y, acc[e][1]);
                acc[e][1] = fmaf(c.w, w3.y, acc[e][1]);
                acc[e][2] = fmaf(c.x, w0.z, acc[e][2]);
                acc[e][2] = fmaf(c.y, w1.z, acc[e][2]);
                acc[e][2] = fmaf(c.z, w2.z, acc[e][2]);
                acc[e][2] = fmaf(c.w, w3.z, acc[e][2]);
                acc[e][3] = fmaf(c.x, w0.w, acc[e][3]);
                acc[e][3] = fmaf(c.y, w1.w, acc[e][3]);
                acc[e][3] = fmaf(c.z, w2.w, acc[e][3]);
                acc[e][3] = fmaf(c.w, w3.w, acc[e][3]);
            }
        }
    }

    // ---- epilogue per edge ----
#pragma unroll
    for (int e = 0; e < 8; e++) {
        size_t edge = e_base + e;
        int dst = edge_index[edge];
        int src = edge_index[N_EDGES + edge];
        const float* Qr = g_Q + (size_t)dst * 64;
        const float* Kr = g_K + (size_t)src * 64;
        const float* Vr = g_V + (size_t)src * 64;

        // conn1 = (Q[dst]+K[src])*Ew ; conn2 = signed sqrt ; conn = relu(conn2+Eb)
        float c1a = (Qr[lane] + Kr[lane]) * acc[e][0];
        float c1b = (Qr[lane + 32] + Kr[lane + 32]) * acc[e][1];
        float c2a = copysignf(sqrtf(fabsf(c1a)), c1a);
        float c2b = copysignf(sqrtf(fabsf(c1b)), c1b);
        float ca = fmaxf(c2a + acc[e][2], 0.f);
        float cb = fmaxf(c2b + acc[e][3], 0.f);

        out_conn[edge * 64 + lane] = ca;
        out_conn[edge * 64 + lane + 32] = cb;

        // score[h] = sum_d conn[h*8+d]*Aw[d][h]; reduce within 8-lane groups
        float sa = ca * aw_a;
        float sb = cb * aw_b;
#pragma unroll
        for (int m = 1; m < 8; m <<= 1) {
            sa += __shfl_xor_sync(0xffffffffu, sa, m);
            sb += __shfl_xor_sync(0xffffffffu, sb, m);
        }
        // clip to [-5,5] then exp — no segment-max needed (bounded range)
        float p0 = __expf(fminf(fmaxf(sa, -CLAMP_V), CLAMP_V));  // head h = lane>>3
        float p1 = __expf(fminf(fmaxf(sb, -CLAMP_V), CLAMP_V));  // head h+4

        // pack payloads for vectorized reductions
        xch[w][lane]       = Vr[lane] * p0;
        xch[w][lane + 32]  = Vr[lane + 32] * p1;
        xch[w][64 + lane]  = ca * p0;
        xch[w][96 + lane]  = cb * p1;
        if (d == 0) { xch[w][128 + h] = p0; xch[w][132 + h] = p1; }
        __syncwarp();

        if (lane < 16) {
            float4 pay = *reinterpret_cast<const float4*>(&xch[w][lane * 4]);
            red_add_v4(&g_agg[(size_t)dst * 64 + lane * 4], pay);
        } else {
            int l2 = lane - 16;
            float4 pay = *reinterpret_cast<const float4*>(&xch[w][64 + l2 * 4]);
            red_add_v4(&g_row[(size_t)dst * 64 + l2 * 4], pay);
        }
        if (lane < 2) {
            float4 pp = *reinterpret_cast<const float4*>(&xch[w][128 + lane * 4]);
            red_add_v4(&g_denom[(size_t)dst * 8 + lane * 4], pp);
        }
        __syncwarp();
    }
}

// ---------------- node finalize: No = (agg + rowV @ Bw) / denom ----------------
__global__ void node_kernel(const float* __restrict__ Bw, float* __restrict__ out_No) {
    int tid = threadIdx.x;
    int n = blockIdx.x * 4 + (tid >> 6);
    if (n >= N_NODES) return;
    int o = tid & 63;
    int h = o >> 3, c = o & 7;
    float s = g_denom[n * 8 + h] + 1e-16f;
    float acc = g_agg[(size_t)n * 64 + o];
#pragma unroll
    for (int dd = 0; dd < 8; dd++)
        acc += g_row[(size_t)n * 64 + h * 8 + dd] * __ldg(&Bw[dd * 64 + h * 8 + c]);
    out_No[(size_t)n * 64 + o] = acc / s;
}

// ---------------- launch ----------------
extern "C" void kernel_launch(void* const* d_in, const int* in_sizes, int n_in,
                              void* d_out, int out_size) {
    const float* x         = (const float*)d_in[0];
    const float* conn_feat = (const float*)d_in[1];
    const int*   edge_idx  = (const int*)d_in[2];
    const float* qkv_w     = (const float*)d_in[3];
    const float* qkv_b     = (const float*)d_in[4];
    const float* E_w       = (const float*)d_in[5];
    const float* E_b       = (const float*)d_in[6];
    const float* Aw        = (const float*)d_in[7];
    const float* Bw        = (const float*)d_in[8];

    float* out      = (float*)d_out;
    float* out_No   = out;                               // [50000, 64]
    float* out_conn = out + (size_t)N_NODES * 64;        // [800000, 64]

    setup_kernel<<<1, 256>>>(E_w);
    zero_kernel<<<2048, 256>>>();
    qkv_kernel<<<(N_NODES + 31) / 32, 256>>>(x, qkv_w, qkv_b);
    edge_kernel<<<N_EDGES / 64, 256>>>(conn_feat, edge_idx, Aw, E_b, out_conn);
    node_kernel<<<(N_NODES + 3) / 4, 256>>>(Bw, out_No);
}

// round 4
// speedup vs baseline: 1.0847x; 1.0847x over previous
#include <cuda_runtime.h>
#include <cstdint>

#define N_NODES 50000
#define N_EDGES 800000
#define CLAMP_V 5.0f

// ---------------- device scratch ----------------
__device__ __align__(128) float g_Q[N_NODES * 64];
__device__ __align__(128) float g_K[N_NODES * 64];
__device__ __align__(128) float g_V[N_NODES * 64];
__device__ __align__(128) float g_denom[N_NODES * 8];
__device__ __align__(128) float g_agg[N_NODES * 64];
__device__ __align__(128) float g_row[N_NODES * 64];
// FFMA2-interleaved E weights, split in two arrays for conflict-free LDS.128:
// g_WA[p*128 + lane*4 + jj*2 + o] = E_w[(jj*32+lane)*64 + 2p + o]      (outputs lane, lane+32)
// g_WB[p*128 + lane*4 + jj*2 + o] = E_w[((jj+2)*32+lane)*64 + 2p + o]  (outputs lane+64, lane+96)
__device__ __align__(128) float g_WA[32 * 128];
__device__ __align__(128) float g_WB[32 * 128];

// packed fp32x2 FMA (sm_100+): d.lo += a.lo*b.lo; d.hi += a.hi*b.hi  (exact fp32 per half)
__device__ __forceinline__ void ffma2(unsigned long long& d, unsigned long long a,
                                      unsigned long long b) {
    asm("fma.rn.f32x2 %0, %1, %2, %0;" : "+l"(d) : "l"(a), "l"(b));
}
__device__ __forceinline__ unsigned long long pack2(float lo, float hi) {
    unsigned long long r;
    asm("mov.b64 %0, {%1, %2};" : "=l"(r) : "f"(lo), "f"(hi));
    return r;
}
__device__ __forceinline__ float2 unpack2(unsigned long long v) {
    float2 r;
    asm("mov.b64 {%0, %1}, %2;" : "=f"(r.x), "=f"(r.y) : "l"(v));
    return r;
}

__device__ __forceinline__ void red_add_v4(float* addr, float4 v) {
    asm volatile("red.global.add.v4.f32 [%0], {%1, %2, %3, %4};"
                 :: "l"(addr), "f"(v.x), "f"(v.y), "f"(v.z), "f"(v.w)
                 : "memory");
}
__device__ __forceinline__ void prefetch_l2(const void* p) {
    asm volatile("prefetch.global.L2 [%0];" :: "l"(p));
}

// ---------------- setup: interleaved E weights ----------------
__global__ void setup_kernel(const float* __restrict__ E_w) {
    for (int i = threadIdx.x; i < 8192; i += 256) {
        int arr = i >> 12;          // 0 = WA, 1 = WB
        int r = i & 4095;
        int p = r >> 7;
        int t = r & 127;
        int lane = t >> 2;
        int jj = (t >> 1) & 1;
        int o = t & 1;
        int outrow = (arr * 2 + jj) * 32 + lane;
        float v = E_w[outrow * 64 + 2 * p + o];
        if (arr) g_WB[r] = v; else g_WA[r] = v;
    }
}

// ---------------- zero accumulators ----------------
__global__ void zero_kernel() {
    size_t tid = (size_t)blockIdx.x * blockDim.x + threadIdx.x;
    size_t nthr = (size_t)gridDim.x * blockDim.x;
    float4 z = make_float4(0.f, 0.f, 0.f, 0.f);
    for (size_t i = tid; i < (size_t)N_NODES * 64 / 4; i += nthr) {
        reinterpret_cast<float4*>(g_agg)[i] = z;
        reinterpret_cast<float4*>(g_row)[i] = z;
    }
    for (size_t i = tid; i < (size_t)N_NODES * 8 / 4; i += nthr) {
        reinterpret_cast<float4*>(g_denom)[i] = z;
    }
}

// ---------------- QKV (FFMA2) ----------------
__global__ __launch_bounds__(256, 2)
void qkv_kernel(const float* __restrict__ x, const float* __restrict__ Wq,
                const float* __restrict__ bq) {
    __shared__ __align__(16) float x_s[32][68];
    __shared__ float out_s[32][193];

    int tid = threadIdx.x;
    int tile = blockIdx.x * 32;

#pragma unroll
    for (int i = 0; i < 8; i++) {
        int idx = tid + i * 256;
        int n = idx >> 6, k = idx & 63;
        int node = tile + n;
        x_s[n][k] = (node < N_NODES) ? x[(size_t)node * 64 + k] : 0.f;
    }
    __syncthreads();

    int w = tid >> 5, lane = tid & 31;
    unsigned long long acc2[24];
#pragma unroll
    for (int t = 0; t < 24; t++) acc2[t] = pack2(__ldg(&bq[w + 8 * t]), 0.f);

    for (int k4 = 0; k4 < 64; k4 += 4) {
        float4 xv = *reinterpret_cast<const float4*>(&x_s[lane][k4]);
        ulonglong2 xp = *reinterpret_cast<ulonglong2*>(&xv);
#pragma unroll
        for (int t = 0; t < 24; t++) {
            float4 wv = *reinterpret_cast<const float4*>(&Wq[(w + 8 * t) * 64 + k4]);
            ulonglong2 wp = *reinterpret_cast<ulonglong2*>(&wv);
            ffma2(acc2[t], xp.x, wp.x);
            ffma2(acc2[t], xp.y, wp.y);
        }
    }

#pragma unroll
    for (int t = 0; t < 24; t++) {
        float2 v = unpack2(acc2[t]);
        out_s[lane][w + 8 * t] = v.x + v.y;
    }
    __syncthreads();

    for (int i = tid; i < 32 * 64; i += 256) {
        int n = i >> 6, col = i & 63;
        int node = tile + n;
        if (node < N_NODES) {
            g_Q[(size_t)node * 64 + col] = out_s[n][col];
            g_K[(size_t)node * 64 + col] = out_s[n][64 + col];
            g_V[(size_t)node * 64 + col] = out_s[n][128 + col];
        }
    }
}

// ---------------- edge kernel: FFMA2 GEMM + fused message + scatter ----------------
__global__ __launch_bounds__(256, 2)
void edge_kernel(const float* __restrict__ conn_feat, const int* __restrict__ edge_index,
                 const float* __restrict__ Aw, const float* __restrict__ E_bias,
                 float* __restrict__ out_conn) {
    __shared__ __align__(16) float WA_s[32 * 128];      // 16 KB
    __shared__ __align__(16) float WB_s[32 * 128];      // 16 KB
    __shared__ __align__(16) float cf_s[8][8][32];      // 8 KB
    __shared__ __align__(16) float xch[8][160];         // 5 KB

    int tid = threadIdx.x;

#pragma unroll
    for (int i = 0; i < 16; i++) {
        WA_s[tid + 256 * i] = g_WA[tid + 256 * i];
        WB_s[tid + 256 * i] = g_WB[tid + 256 * i];
    }
    __syncthreads();

    int w = tid >> 5, lane = tid & 31;
    int h = lane >> 3, d = lane & 7;

    float b0 = E_bias[lane];
    float b1 = E_bias[lane + 32];
    float b2 = E_bias[lane + 64];
    float b3 = E_bias[lane + 96];
    float aw_a = __ldg(&Aw[d * 8 + h]);
    float aw_b = __ldg(&Aw[d * 8 + h + 4]);

    size_t e_base = ((size_t)blockIdx.x * 8 + w) * 8;

    // lanes 0..7 hold dst/src of their edge; prefetch Q/K/V rows into L2 so the
    // epilogue gathers hit L2 instead of stalling ~600 cyc on DRAM.
    int my_dst = 0, my_src = 0;
    if (lane < 8) {
        my_dst = edge_index[e_base + lane];
        my_src = edge_index[N_EDGES + e_base + lane];
        const float* q = g_Q + (size_t)my_dst * 64;
        const float* k = g_K + (size_t)my_src * 64;
        const float* v = g_V + (size_t)my_src * 64;
        prefetch_l2(q); prefetch_l2(q + 32);
        prefetch_l2(k); prefetch_l2(k + 32);
        prefetch_l2(v); prefetch_l2(v + 32);
    }

    // acc pairs: (even-k partial, odd-k partial) per output component
    unsigned long long acc2[8][4];
#pragma unroll
    for (int e = 0; e < 8; e++) {
        acc2[e][0] = pack2(b0, 0.f);
        acc2[e][1] = pack2(b1, 0.f);
        acc2[e][2] = pack2(b2, 0.f);
        acc2[e][3] = pack2(b3, 0.f);
    }

    // ---- GEMM via fma.rn.f32x2 ----
    for (int kt = 0; kt < 64; kt += 32) {
        __syncwarp();
#pragma unroll
        for (int e = 0; e < 8; e++)
            cf_s[w][e][lane] = __ldcs(&conn_feat[(e_base + e) * 64 + kt + lane]);
        __syncwarp();
#pragma unroll 4
        for (int k4 = 0; k4 < 32; k4 += 4) {
            int p = (kt + k4) >> 1;                     // k-pair index
            float4 wa0 = *reinterpret_cast<const float4*>(&WA_s[p * 128 + lane * 4]);
            float4 wb0 = *reinterpret_cast<const float4*>(&WB_s[p * 128 + lane * 4]);
            float4 wa1 = *reinterpret_cast<const float4*>(&WA_s[(p + 1) * 128 + lane * 4]);
            float4 wb1 = *reinterpret_cast<const float4*>(&WB_s[(p + 1) * 128 + lane * 4]);
            ulonglong2 a0 = *reinterpret_cast<ulonglong2*>(&wa0);
            ulonglong2 bb0 = *reinterpret_cast<ulonglong2*>(&wb0);
            ulonglong2 a1 = *reinterpret_cast<ulonglong2*>(&wa1);
            ulonglong2 bb1 = *reinterpret_cast<ulonglong2*>(&wb1);
#pragma unroll
            for (int e = 0; e < 8; e++) {
                float4 c = *reinterpret_cast<const float4*>(&cf_s[w][e][k4]);
                ulonglong2 cp = *reinterpret_cast<ulonglong2*>(&c);
                ffma2(acc2[e][0], cp.x, a0.x);
                ffma2(acc2[e][1], cp.x, a0.y);
                ffma2(acc2[e][2], cp.x, bb0.x);
                ffma2(acc2[e][3], cp.x, bb0.y);
                ffma2(acc2[e][0], cp.y, a1.x);
                ffma2(acc2[e][1], cp.y, a1.y);
                ffma2(acc2[e][2], cp.y, bb1.x);
                ffma2(acc2[e][3], cp.y, bb1.y);
            }
        }
    }

    // ---- epilogue per edge ----
#pragma unroll
    for (int e = 0; e < 8; e++) {
        size_t edge = e_base + e;
        int dst = __shfl_sync(0xffffffffu, my_dst, e);
        int src = __shfl_sync(0xffffffffu, my_src, e);
        const float* Qr = g_Q + (size_t)dst * 64;
        const float* Kr = g_K + (size_t)src * 64;
        const float* Vr = g_V + (size_t)src * 64;

        float2 v0 = unpack2(acc2[e][0]);
        float2 v1 = unpack2(acc2[e][1]);
        float2 v2 = unpack2(acc2[e][2]);
        float2 v3 = unpack2(acc2[e][3]);
        float ew0 = v0.x + v0.y;   // Eh[lane]       (Ew)
        float ew1 = v1.x + v1.y;   // Eh[lane+32]    (Ew)
        float eb0 = v2.x + v2.y;   // Eh[lane+64]    (Eb)
        float eb1 = v3.x + v3.y;   // Eh[lane+96]    (Eb)

        float c1a = (Qr[lane] + Kr[lane]) * ew0;
        float c1b = (Qr[lane + 32] + Kr[lane + 32]) * ew1;
        float c2a = copysignf(sqrtf(fabsf(c1a)), c1a);
        float c2b = copysignf(sqrtf(fabsf(c1b)), c1b);
        float ca = fmaxf(c2a + eb0, 0.f);
        float cb = fmaxf(c2b + eb1, 0.f);

        __stcs(&out_conn[edge * 64 + lane], ca);
        __stcs(&out_conn[edge * 64 + lane + 32], cb);

        float sa = ca * aw_a;
        float sb = cb * aw_b;
#pragma unroll
        for (int m = 1; m < 8; m <<= 1) {
            sa += __shfl_xor_sync(0xffffffffu, sa, m);
            sb += __shfl_xor_sync(0xffffffffu, sb, m);
        }
        float p0 = __expf(fminf(fmaxf(sa, -CLAMP_V), CLAMP_V));
        float p1 = __expf(fminf(fmaxf(sb, -CLAMP_V), CLAMP_V));

        xch[w][lane]       = Vr[lane] * p0;
        xch[w][lane + 32]  = Vr[lane + 32] * p1;
        xch[w][64 + lane]  = ca * p0;
        xch[w][96 + lane]  = cb * p1;
        if (d == 0) { xch[w][128 + h] = p0; xch[w][132 + h] = p1; }
        __syncwarp();

        if (lane < 16) {
            float4 pay = *reinterpret_cast<const float4*>(&xch[w][lane * 4]);
            red_add_v4(&g_agg[(size_t)dst * 64 + lane * 4], pay);
        } else {
            int l2i = lane - 16;
            float4 pay = *reinterpret_cast<const float4*>(&xch[w][64 + l2i * 4]);
            red_add_v4(&g_row[(size_t)dst * 64 + l2i * 4], pay);
        }
        if (lane < 2) {
            float4 pp = *reinterpret_cast<const float4*>(&xch[w][128 + lane * 4]);
            red_add_v4(&g_denom[(size_t)dst * 8 + lane * 4], pp);
        }
        __syncwarp();
    }
}

// ---------------- node finalize ----------------
__global__ void node_kernel(const float* __restrict__ Bw, float* __restrict__ out_No) {
    int tid = threadIdx.x;
    int n = blockIdx.x * 4 + (tid >> 6);
    if (n >= N_NODES) return;
    int o = tid & 63;
    int h = o >> 3, c = o & 7;
    float s = g_denom[n * 8 + h] + 1e-16f;
    float acc = g_agg[(size_t)n * 64 + o];
#pragma unroll
    for (int dd = 0; dd < 8; dd++)
        acc += g_row[(size_t)n * 64 + h * 8 + dd] * __ldg(&Bw[dd * 64 + h * 8 + c]);
    out_No[(size_t)n * 64 + o] = acc / s;
}

// ---------------- launch ----------------
extern "C" void kernel_launch(void* const* d_in, const int* in_sizes, int n_in,
                              void* d_out, int out_size) {
    const float* x         = (const float*)d_in[0];
    const float* conn_feat = (const float*)d_in[1];
    const int*   edge_idx  = (const int*)d_in[2];
    const float* qkv_w     = (const float*)d_in[3];
    const float* qkv_b     = (const float*)d_in[4];
    const float* E_w       = (const float*)d_in[5];
    const float* E_b       = (const float*)d_in[6];
    const float* Aw        = (const float*)d_in[7];
    const float* Bw        = (const float*)d_in[8];

    float* out      = (float*)d_out;
    float* out_No   = out;
    float* out_conn = out + (size_t)N_NODES * 64;

    setup_kernel<<<1, 256>>>(E_w);
    zero_kernel<<<2048, 256>>>();
    qkv_kernel<<<(N_NODES + 31) / 32, 256>>>(x, qkv_w, qkv_b);
    edge_kernel<<<N_EDGES / 64, 256>>>(conn_feat, edge_idx, Aw, E_b, out_conn);
    node_kernel<<<(N_NODES + 3) / 4, 256>>>(Bw, out_No);
}